// round 1
// baseline (speedup 1.0000x reference)
#include <cuda_runtime.h>
#include <math.h>

// Problem constants
// B=8, S=8192, D=1024, G=512 groups of GS=16, K=64 selected, H=16 heads, HD=64, DH4=256

// ---------------- scratch (device globals; no allocs allowed) ----------------
__device__ float g_groups[8 * 512 * 1024];   // [B*G][D] group means (16 MB)
__device__ float g_scores[8 * 512];          // [B*G]
__device__ int   g_topidx[8 * 64];           // [B*K]
__device__ float g_sel[512 * 1024];          // [B*K][D] gathered group reps
__device__ float g_q[512 * 1024];
__device__ float g_k[512 * 1024];
__device__ float g_v[512 * 1024];
__device__ float g_ctx[512 * 1024];
__device__ float g_outg[512 * 1024];

// ---------------- 1) group mean-pool + zero-fill output ----------------
// grid 4096 (b*512+g), block 256. Each block: 16 rows x 1024 cols.
// Reads 64KB, writes 64KB zeros to out + 4KB means. This is the HBM-bound kernel.
__global__ __launch_bounds__(256) void pool_zero_kernel(const float* __restrict__ hid,
                                                        float* __restrict__ out) {
    int blk = blockIdx.x;
    int b = blk >> 9, g = blk & 511;
    int t = threadIdx.x;  // float4 column chunk 0..255
    const float4* in4 = (const float4*)hid;
    float4* out4 = (float4*)out;
    float4* grp4 = (float4*)g_groups;
    int base = (b * 8192 + g * 16) * 256 + t;
    float4 s = make_float4(0.f, 0.f, 0.f, 0.f);
    float4 z = make_float4(0.f, 0.f, 0.f, 0.f);
#pragma unroll
    for (int r = 0; r < 16; r++) {
        float4 v = in4[base + r * 256];
        s.x += v.x; s.y += v.y; s.z += v.z; s.w += v.w;
        out4[base + r * 256] = z;
    }
    const float inv = 1.0f / 16.0f;
    s.x *= inv; s.y *= inv; s.z *= inv; s.w *= inv;
    grp4[(b * 512 + g) * 256 + t] = s;
}

// ---------------- 2) scorer GEMM: scores = relu(groups@Ws1 + bs1)@Ws2 + bs2 ----------------
// Block tile M=32, full N=256, BK=16. blockDim(32,8): tx covers 32x8 cols, ty covers 8x4 rows.
// Fused ReLU + Ws2 contraction + bias in epilogue (block-level reduce to 32 scores).
__global__ __launch_bounds__(256) void scorer_kernel(const float* __restrict__ Ws1,
                                                     const float* __restrict__ bs1,
                                                     const float* __restrict__ Ws2,
                                                     const float* __restrict__ bs2) {
    __shared__ float As[16][36];    // [k][m], padded
    __shared__ float Bs[16][256];   // [k][n]
    __shared__ float red[1024];     // 32 rows x 32 tx
    int tx = threadIdx.x, ty = threadIdx.y;
    int tid = ty * 32 + tx;
    int rowBase = blockIdx.x * 32;
    float acc[4][8];
#pragma unroll
    for (int i = 0; i < 4; i++)
#pragma unroll
        for (int j = 0; j < 8; j++) acc[i][j] = 0.f;

    const float4* A4 = (const float4*)g_groups;
    for (int kt = 0; kt < 1024; kt += 16) {
        if (tid < 128) {
            int row = tid >> 2, c4 = tid & 3;
            float4 a = A4[(rowBase + row) * 256 + (kt >> 2) + c4];
            As[c4 * 4 + 0][row] = a.x;
            As[c4 * 4 + 1][row] = a.y;
            As[c4 * 4 + 2][row] = a.z;
            As[c4 * 4 + 3][row] = a.w;
        }
#pragma unroll
        for (int i = 0; i < 4; i++) {
            int e = tid + 256 * i;
            int row = e >> 6, c4 = e & 63;
            *(float4*)&Bs[row][c4 * 4] = *(const float4*)&Ws1[(kt + row) * 256 + c4 * 4];
        }
        __syncthreads();
#pragma unroll
        for (int k = 0; k < 16; k++) {
            float4 a = *(float4*)&As[k][ty * 4];
            float4 b0 = *(float4*)&Bs[k][tx * 8];
            float4 b1 = *(float4*)&Bs[k][tx * 8 + 4];
            float av[4] = {a.x, a.y, a.z, a.w};
            float bv[8] = {b0.x, b0.y, b0.z, b0.w, b1.x, b1.y, b1.z, b1.w};
#pragma unroll
            for (int i = 0; i < 4; i++)
#pragma unroll
                for (int j = 0; j < 8; j++) acc[i][j] = fmaf(av[i], bv[j], acc[i][j]);
        }
        __syncthreads();
    }
    // epilogue: relu + bias + contract with Ws2
    float part[4] = {0.f, 0.f, 0.f, 0.f};
#pragma unroll
    for (int j = 0; j < 8; j++) {
        int col = tx * 8 + j;
        float w2 = Ws2[col];
        float b1v = bs1[col];
#pragma unroll
        for (int i = 0; i < 4; i++) {
            float v = acc[i][j] + b1v;
            v = fmaxf(v, 0.f);
            part[i] = fmaf(v, w2, part[i]);
        }
    }
#pragma unroll
    for (int i = 0; i < 4; i++) red[(ty * 4 + i) * 32 + tx] = part[i];
    __syncthreads();
    if (tid < 32) {
        float s = bs2[0];
#pragma unroll
        for (int x = 0; x < 32; x++) s += red[tid * 32 + x];
        g_scores[rowBase + tid] = s;
    }
}

// ---------------- 3) top-64 selection (softmax skipped: monotonic) + gather ----------------
// Tie-break: equal values -> smaller index (matches jax.lax.top_k stability).
__global__ __launch_bounds__(512) void topk_gather_kernel() {
    int b = blockIdx.x;
    int t = threadIdx.x;
    __shared__ float vals[512];
    __shared__ float rv[512];
    __shared__ int ri[512];
    __shared__ int chosen[64];
    vals[t] = g_scores[b * 512 + t];
    __syncthreads();
    for (int it = 0; it < 64; it++) {
        rv[t] = vals[t];
        ri[t] = t;
        __syncthreads();
        for (int s = 256; s > 0; s >>= 1) {
            if (t < s) {
                float v2 = rv[t + s];
                int i2 = ri[t + s];
                if (v2 > rv[t] || (v2 == rv[t] && i2 < ri[t])) { rv[t] = v2; ri[t] = i2; }
            }
            __syncthreads();
        }
        if (t == 0) {
            int c = ri[0];
            chosen[it] = c;
            g_topidx[b * 64 + it] = c;
            vals[c] = -3.4e38f;
        }
        __syncthreads();
    }
    // gather selected group reps into g_sel
    for (int kk = 0; kk < 64; kk++) {
        int idx = chosen[kk];
        const float* src = &g_groups[(b * 512 + idx) * 1024];
        float* dst = &g_sel[(b * 64 + kk) * 1024];
        for (int off = t; off < 1024; off += 512) dst[off] = src[off];
    }
}

// ---------------- 4) generic 64x64 tiled GEMM (M=512, N=1024, K=1024) ----------------
// mode 0: A=g_sel, C=g_q/g_k/g_v per blockIdx.z (Wq/Wk/Wv in B0/B1/B2)
// mode 1: A=g_ctx, C=g_outg (Wo in B0)
__global__ __launch_bounds__(256) void gemm64_kernel(int mode,
                                                     const float* __restrict__ B0,
                                                     const float* __restrict__ B1,
                                                     const float* __restrict__ B2) {
    const float* A = (mode == 0) ? g_sel : g_ctx;
    const float* Bm = (blockIdx.z == 0) ? B0 : ((blockIdx.z == 1) ? B1 : B2);
    float* Cm;
    if (mode == 0)
        Cm = (blockIdx.z == 0) ? g_q : ((blockIdx.z == 1) ? g_k : g_v);
    else
        Cm = g_outg;
    const int N = 1024, Kd = 1024;
    __shared__ float As[16][68];  // [k][m] padded
    __shared__ float Bs[16][64];  // [k][n]
    int tx = threadIdx.x, ty = threadIdx.y;  // 16 x 16
    int tid = ty * 16 + tx;
    int rowBase = blockIdx.x * 64, colBase = blockIdx.y * 64;
    float acc[4][4];
#pragma unroll
    for (int i = 0; i < 4; i++)
#pragma unroll
        for (int j = 0; j < 4; j++) acc[i][j] = 0.f;

    for (int kt = 0; kt < Kd; kt += 16) {
        {
            int row = tid >> 2, c4 = tid & 3;
            float4 a = *(const float4*)&A[(rowBase + row) * Kd + kt + c4 * 4];
            As[c4 * 4 + 0][row] = a.x;
            As[c4 * 4 + 1][row] = a.y;
            As[c4 * 4 + 2][row] = a.z;
            As[c4 * 4 + 3][row] = a.w;
        }
        {
            int row = tid >> 4, c4 = tid & 15;
            *(float4*)&Bs[row][c4 * 4] = *(const float4*)&Bm[(kt + row) * N + colBase + c4 * 4];
        }
        __syncthreads();
#pragma unroll
        for (int k = 0; k < 16; k++) {
            float4 a = *(float4*)&As[k][ty * 4];
            float4 b = *(float4*)&Bs[k][tx * 4];
            float av[4] = {a.x, a.y, a.z, a.w};
            float bv[4] = {b.x, b.y, b.z, b.w};
#pragma unroll
            for (int i = 0; i < 4; i++)
#pragma unroll
                for (int j = 0; j < 4; j++) acc[i][j] = fmaf(av[i], bv[j], acc[i][j]);
        }
        __syncthreads();
    }
#pragma unroll
    for (int i = 0; i < 4; i++) {
        float4 o = make_float4(acc[i][0], acc[i][1], acc[i][2], acc[i][3]);
        *(float4*)&Cm[(rowBase + ty * 4 + i) * N + colBase + tx * 4] = o;
    }
}

// ---------------- 5) small MHA over the 64 selected reps ----------------
// grid (H=16, B=8), block 64: thread q owns query row q of this (b,h).
__global__ __launch_bounds__(64) void attn_kernel() {
    __shared__ float Ks[4096];
    __shared__ float Vs[4096];
    __shared__ float Ssm[4096];  // S/P stored [j][q] for conflict-free column access
    int h = blockIdx.x, b = blockIdx.y;
    int q = threadIdx.x;
    const float4* K4 = (const float4*)g_k;
    const float4* V4 = (const float4*)g_v;
    float4* Ks4 = (float4*)Ks;
    float4* Vs4 = (float4*)Vs;
    for (int i = q; i < 1024; i += 64) {
        int j = i >> 4, c = i & 15;
        Ks4[i] = K4[(b * 64 + j) * 256 + h * 16 + c];
        Vs4[i] = V4[(b * 64 + j) * 256 + h * 16 + c];
    }
    float Qr[64];
    {
        const float4* Q4 = (const float4*)g_q;
#pragma unroll
        for (int c = 0; c < 16; c++) {
            float4 v = Q4[(b * 64 + q) * 256 + h * 16 + c];
            Qr[c * 4 + 0] = v.x; Qr[c * 4 + 1] = v.y;
            Qr[c * 4 + 2] = v.z; Qr[c * 4 + 3] = v.w;
        }
    }
    __syncthreads();
    float m = -3.4e38f;
    for (int j = 0; j < 64; j++) {
        float s = 0.f;
#pragma unroll
        for (int d = 0; d < 64; d++) s = fmaf(Qr[d], Ks[j * 64 + d], s);
        s *= 0.125f;  // 1/sqrt(64)
        Ssm[j * 64 + q] = s;
        m = fmaxf(m, s);
    }
    float l = 0.f;
    for (int j = 0; j < 64; j++) {
        float e = __expf(Ssm[j * 64 + q] - m);
        Ssm[j * 64 + q] = e;
        l += e;
    }
    float inv = 1.f / l;
    float acc[64];
#pragma unroll
    for (int d = 0; d < 64; d++) acc[d] = 0.f;
    for (int j = 0; j < 64; j++) {
        float p = Ssm[j * 64 + q] * inv;
#pragma unroll
        for (int d = 0; d < 64; d++) acc[d] = fmaf(p, Vs[j * 64 + d], acc[d]);
    }
    __syncthreads();  // everyone done reading Ks before reuse
    for (int d = 0; d < 64; d++) Ks[q * 64 + d] = acc[d];
    __syncthreads();
    float4* C4 = (float4*)g_ctx;
    for (int i = q; i < 1024; i += 64) {
        int j = i >> 4, c = i & 15;
        C4[(b * 64 + j) * 256 + h * 16 + c] = Ks4[i];
    }
}

// ---------------- 6) scatter-broadcast selected group outputs ----------------
// grid 512 (b*64+k), block 256: replicate out_g row to its 16 sequence positions.
__global__ __launch_bounds__(256) void scatter_kernel(float* __restrict__ out) {
    int r = blockIdx.x;
    int b = r >> 6;
    int idx = g_topidx[r];
    int t = threadIdx.x;
    const float4* og4 = (const float4*)g_outg;
    float4* out4 = (float4*)out;
    float4 v = og4[r * 256 + t];
    int base = (b * 8192 + idx * 16) * 256 + t;
#pragma unroll
    for (int rr = 0; rr < 16; rr++) out4[base + rr * 256] = v;
}

// ---------------- launch ----------------
extern "C" void kernel_launch(void* const* d_in, const int* in_sizes, int n_in,
                              void* d_out, int out_size) {
    const float* hid = (const float*)d_in[0];
    const float* Wq  = (const float*)d_in[1];
    const float* Wk  = (const float*)d_in[2];
    const float* Wv  = (const float*)d_in[3];
    const float* Wo  = (const float*)d_in[4];
    const float* Ws1 = (const float*)d_in[5];
    const float* bs1 = (const float*)d_in[6];
    const float* Ws2 = (const float*)d_in[7];
    const float* bs2 = (const float*)d_in[8];
    float* out = (float*)d_out;

    pool_zero_kernel<<<4096, 256>>>(hid, out);
    scorer_kernel<<<128, dim3(32, 8)>>>(Ws1, bs1, Ws2, bs2);
    topk_gather_kernel<<<8, 512>>>();
    gemm64_kernel<<<dim3(8, 16, 3), dim3(16, 16)>>>(0, Wq, Wk, Wv);
    attn_kernel<<<dim3(16, 8), 64>>>();
    gemm64_kernel<<<dim3(8, 16, 1), dim3(16, 16)>>>(1, Wo, Wo, Wo);
    scatter_kernel<<<512, 256>>>(out);
}